// round 1
// baseline (speedup 1.0000x reference)
#include <cuda_runtime.h>

#define N_B 64
#define HW_ 1024
#define D_  512
#define K_  64
#define ROWS (N_B*HW_)
#define EPSF 1e-12f

// Scratch (allocation-free rule: __device__ globals)
__device__ float g_a[(size_t)ROWS * K_];      // softmax assignments [rows, K]
__device__ float g_asum[N_B * K_];            // sum over hw of a     [N, K]
__device__ float g_colsq[N_B * K_];           // per-(n,k) sum of v^2 [N, K]

// ---------------------------------------------------------------------------
// K0: zero accumulators (must re-zero every graph replay)
// ---------------------------------------------------------------------------
__global__ void zero_kernel() {
    int t = blockIdx.x * blockDim.x + threadIdx.x;
    if (t < N_B * K_) { g_asum[t] = 0.f; g_colsq[t] = 0.f; }
}

// ---------------------------------------------------------------------------
// K1: assignment GEMM (65536 x 64 x 512) + softmax + a_sum
// Block: 256 threads (16x16), tile BM=128 rows, BN=64 cols, BK=32.
// Thread micro-tile: 8 rows x 4 cols. Row's 64 cols live across 16 lanes
// (tx = tid & 15) -> softmax reductions via xor-shuffle within 16-lane group.
// ---------------------------------------------------------------------------
__launch_bounds__(256, 4)
__global__ void assign_kernel(const float* __restrict__ x,
                              const float* __restrict__ Wc,
                              const float* __restrict__ bc) {
    __shared__ float As[32][132];   // [d_k][row], 132 pad: rows 16B-aligned (528B)
    __shared__ float Bs[32][64];    // [d_k][col]
    __shared__ float red[16][64];

    const int tid = threadIdx.x;
    const int tx = tid & 15;        // col group
    const int ty = tid >> 4;        // row group
    const int row0 = blockIdx.x * 128;
    const int n = row0 >> 10;       // 1024 rows per n, blocks aligned

    float acc[8][4];
#pragma unroll
    for (int i = 0; i < 8; i++)
#pragma unroll
        for (int j = 0; j < 4; j++) acc[i][j] = 0.f;

    for (int kt = 0; kt < D_; kt += 32) {
        // x tile: 128 rows x 32 d, stored transposed As[d][row]
        {
            int r = tid >> 3;            // 0..31
            int c = (tid & 7) * 4;       // 0..28
#pragma unroll
            for (int p = 0; p < 4; p++) {
                int rr = r + p * 32;
                float4 v = *(const float4*)(x + (size_t)(row0 + rr) * D_ + kt + c);
                As[c + 0][rr] = v.x; As[c + 1][rr] = v.y;
                As[c + 2][rr] = v.z; As[c + 3][rr] = v.w;
            }
        }
        // W tile: 32 d x 64 k, direct copy
        {
            int r = tid >> 4;            // 0..15
            int c = (tid & 15) * 4;
#pragma unroll
            for (int p = 0; p < 2; p++) {
                int rr = r + p * 16;
                *(float4*)&Bs[rr][c] = *(const float4*)(Wc + (size_t)(kt + rr) * K_ + c);
            }
        }
        __syncthreads();
#pragma unroll
        for (int kk = 0; kk < 32; kk++) {
            float af[8], bf[4];
            *(float4*)&af[0] = *(const float4*)&As[kk][ty * 8];
            *(float4*)&af[4] = *(const float4*)&As[kk][ty * 8 + 4];
            *(float4*)&bf[0] = *(const float4*)&Bs[kk][tx * 4];
#pragma unroll
            for (int i = 0; i < 8; i++)
#pragma unroll
                for (int j = 0; j < 4; j++)
                    acc[i][j] = fmaf(af[i], bf[j], acc[i][j]);
        }
        __syncthreads();
    }

    // epilogue: + bias, softmax over 64 cols (16 lanes x 4 cols), store a
    float bfr[4];
    *(float4*)bfr = *(const float4*)(bc + tx * 4);
    float asum_loc[4] = {0.f, 0.f, 0.f, 0.f};
#pragma unroll
    for (int i = 0; i < 8; i++) {
        float c0 = acc[i][0] + bfr[0];
        float c1 = acc[i][1] + bfr[1];
        float c2 = acc[i][2] + bfr[2];
        float c3 = acc[i][3] + bfr[3];
        float m = fmaxf(fmaxf(c0, c1), fmaxf(c2, c3));
#pragma unroll
        for (int o = 1; o < 16; o <<= 1)
            m = fmaxf(m, __shfl_xor_sync(0xffffffffu, m, o));
        float e0 = __expf(c0 - m), e1 = __expf(c1 - m);
        float e2 = __expf(c2 - m), e3 = __expf(c3 - m);
        float s = e0 + e1 + e2 + e3;
#pragma unroll
        for (int o = 1; o < 16; o <<= 1)
            s += __shfl_xor_sync(0xffffffffu, s, o);
        float inv = 1.0f / s;
        e0 *= inv; e1 *= inv; e2 *= inv; e3 *= inv;
        int row = row0 + ty * 8 + i;
        *(float4*)(g_a + (size_t)row * K_ + tx * 4) = make_float4(e0, e1, e2, e3);
        asum_loc[0] += e0; asum_loc[1] += e1; asum_loc[2] += e2; asum_loc[3] += e3;
    }
    // block-level a_sum reduction, one atomic per (block, k)
#pragma unroll
    for (int j = 0; j < 4; j++) red[ty][tx * 4 + j] = asum_loc[j];
    __syncthreads();
    if (tid < 64) {
        float s = 0.f;
#pragma unroll
        for (int t2 = 0; t2 < 16; t2++) s += red[t2][tid];
        atomicAdd(&g_asum[n * K_ + tid], s);
    }
}

// ---------------------------------------------------------------------------
// K2: per-batch VLAD GEMM  V[d,k] = sum_hw x[n,hw,d] * a[n,hw,k]
// Grid (4 d-tiles, 64 n). BM=128 (d), BN=64 (k), BK=32 (hw).
// Epilogue: V += a_sum[n,k]*C[d,k]; write to out [N,D,K]; accumulate colsq.
// ---------------------------------------------------------------------------
__launch_bounds__(256, 4)
__global__ void vlad_kernel(const float* __restrict__ x,
                            const float* __restrict__ Cc,
                            float* __restrict__ out) {
    __shared__ float As[32][128];   // [hw_k][d] -- natural load, no transpose
    __shared__ float Bs[32][64];    // [hw_k][k]
    __shared__ float red[16][64];

    const int tid = threadIdx.x;
    const int tx = tid & 15;
    const int ty = tid >> 4;
    const int n = blockIdx.y;
    const int m0 = blockIdx.x * 128;

    const float* xn = x + (size_t)n * HW_ * D_;
    const float* an = g_a + (size_t)n * HW_ * K_;

    float acc[8][4];
#pragma unroll
    for (int i = 0; i < 8; i++)
#pragma unroll
        for (int j = 0; j < 4; j++) acc[i][j] = 0.f;

    for (int kt = 0; kt < HW_; kt += 32) {
        {
            int r = tid >> 5;            // 0..7
            int c = (tid & 31) * 4;      // 0..124
#pragma unroll
            for (int p = 0; p < 4; p++) {
                int rr = r + p * 8;
                *(float4*)&As[rr][c] =
                    *(const float4*)(xn + (size_t)(kt + rr) * D_ + m0 + c);
            }
        }
        {
            int r = tid >> 4;
            int c = (tid & 15) * 4;
#pragma unroll
            for (int p = 0; p < 2; p++) {
                int rr = r + p * 16;
                *(float4*)&Bs[rr][c] = *(const float4*)(an + (size_t)(kt + rr) * K_ + c);
            }
        }
        __syncthreads();
#pragma unroll
        for (int kk = 0; kk < 32; kk++) {
            float af[8], bf[4];
            *(float4*)&af[0] = *(const float4*)&As[kk][ty * 8];
            *(float4*)&af[4] = *(const float4*)&As[kk][ty * 8 + 4];
            *(float4*)&bf[0] = *(const float4*)&Bs[kk][tx * 4];
#pragma unroll
            for (int i = 0; i < 8; i++)
#pragma unroll
                for (int j = 0; j < 4; j++)
                    acc[i][j] = fmaf(af[i], bf[j], acc[i][j]);
        }
        __syncthreads();
    }

    // epilogue: + a_sum*C, write v, accumulate column sum-of-squares
    float asv[4];
    *(float4*)asv = *(const float4*)(g_asum + n * K_ + tx * 4);
    float sq[4] = {0.f, 0.f, 0.f, 0.f};
#pragma unroll
    for (int i = 0; i < 8; i++) {
        int d = m0 + ty * 8 + i;
        float4 cc = *(const float4*)(Cc + (size_t)d * K_ + tx * 4);
        float v0 = fmaf(asv[0], cc.x, acc[i][0]);
        float v1 = fmaf(asv[1], cc.y, acc[i][1]);
        float v2 = fmaf(asv[2], cc.z, acc[i][2]);
        float v3 = fmaf(asv[3], cc.w, acc[i][3]);
        sq[0] = fmaf(v0, v0, sq[0]); sq[1] = fmaf(v1, v1, sq[1]);
        sq[2] = fmaf(v2, v2, sq[2]); sq[3] = fmaf(v3, v3, sq[3]);
        *(float4*)(out + ((size_t)n * D_ + d) * K_ + tx * 4) =
            make_float4(v0, v1, v2, v3);
    }
#pragma unroll
    for (int j = 0; j < 4; j++) red[ty][tx * 4 + j] = sq[j];
    __syncthreads();
    if (tid < 64) {
        float s = 0.f;
#pragma unroll
        for (int t2 = 0; t2 < 16; t2++) s += red[t2][tid];
        atomicAdd(&g_colsq[n * K_ + tid], s);
    }
}

// ---------------------------------------------------------------------------
// K3: two-level L2 normalization, in place on out. One block per n.
// intra: w = v / sqrt(S_k + eps); after intra, col sumsq = S_k/(S_k+eps)
// global: / sqrt( sum_k S_k/(S_k+eps) + eps )
// ---------------------------------------------------------------------------
__global__ void norm_kernel(float* __restrict__ out) {
    __shared__ float sc[64];
    __shared__ float contrib[64];
    __shared__ float ginv;

    const int n = blockIdx.x;
    const int tid = threadIdx.x;

    if (tid < 64) {
        float S = g_colsq[n * K_ + tid];
        sc[tid] = rsqrtf(S + EPSF);
        contrib[tid] = S / (S + EPSF);
    }
    __syncthreads();
    if (tid == 0) {
        float g = 0.f;
#pragma unroll
        for (int k = 0; k < 64; k++) g += contrib[k];
        ginv = rsqrtf(g + EPSF);
    }
    __syncthreads();
    if (tid < 64) sc[tid] *= ginv;
    __syncthreads();

    float* po = out + (size_t)n * D_ * K_;
    for (int e = tid * 4; e < D_ * K_; e += blockDim.x * 4) {
        float4 v = *(float4*)(po + e);
        int k = e & 63;            // e multiple of 4; 64 | row length
        v.x *= sc[k + 0]; v.y *= sc[k + 1];
        v.z *= sc[k + 2]; v.w *= sc[k + 3];
        *(float4*)(po + e) = v;
    }
}

// ---------------------------------------------------------------------------
extern "C" void kernel_launch(void* const* d_in, const int* in_sizes, int n_in,
                              void* d_out, int out_size) {
    const float* x  = (const float*)d_in[0];   // [64,32,32,512]
    const float* W  = (const float*)d_in[1];   // [512,64]
    const float* b  = (const float*)d_in[2];   // [64]
    const float* C  = (const float*)d_in[3];   // [512,64]
    float* out = (float*)d_out;                // [64, 32768]

    zero_kernel<<<16, 256>>>();
    assign_kernel<<<ROWS / 128, 256>>>(x, W, b);
    dim3 g2(D_ / 128, N_B);
    vlad_kernel<<<g2, 256>>>(x, C, out);
    norm_kernel<<<N_B, 256>>>(out);
}

// round 2
// speedup vs baseline: 1.0022x; 1.0022x over previous
#include <cuda_runtime.h>

#define N_B 64
#define HW_ 1024
#define D_  512
#define K_  64
#define ROWS (N_B*HW_)
#define EPSF 1e-12f

// Scratch (allocation-free rule: __device__ globals)
__device__ float g_a[(size_t)ROWS * K_];      // softmax assignments [rows, K]
__device__ float g_asum[N_B * K_];            // sum over hw of a     [N, K]
__device__ float g_colsq[N_B * K_];           // per-(n,k) sum of v^2 [N, K]

// ---------------------------------------------------------------------------
// K0: zero accumulators (must re-zero every graph replay)
// ---------------------------------------------------------------------------
__global__ void zero_kernel() {
    int t = blockIdx.x * blockDim.x + threadIdx.x;
    if (t < N_B * K_) { g_asum[t] = 0.f; g_colsq[t] = 0.f; }
}

// ---------------------------------------------------------------------------
// K1: assignment GEMM (65536 x 64 x 512) + softmax + a_sum
// Block: 256 threads (16x16), tile BM=128 rows, BN=64 cols, BK=32.
// Thread micro-tile: 8 rows x 4 cols. Row's 64 cols live across 16 lanes
// (tx = tid & 15) -> softmax reductions via xor-shuffle within 16-lane group.
// ---------------------------------------------------------------------------
__launch_bounds__(256, 4)
__global__ void assign_kernel(const float* __restrict__ x,
                              const float* __restrict__ Wc,
                              const float* __restrict__ bc) {
    __shared__ float As[32][132];   // [d_k][row], 132 pad: rows 16B-aligned (528B)
    __shared__ float Bs[32][64];    // [d_k][col]
    __shared__ float red[16][64];

    const int tid = threadIdx.x;
    const int tx = tid & 15;        // col group
    const int ty = tid >> 4;        // row group
    const int row0 = blockIdx.x * 128;
    const int n = row0 >> 10;       // 1024 rows per n, blocks aligned

    float acc[8][4];
#pragma unroll
    for (int i = 0; i < 8; i++)
#pragma unroll
        for (int j = 0; j < 4; j++) acc[i][j] = 0.f;

    for (int kt = 0; kt < D_; kt += 32) {
        // x tile: 128 rows x 32 d, stored transposed As[d][row]
        {
            int r = tid >> 3;            // 0..31
            int c = (tid & 7) * 4;       // 0..28
#pragma unroll
            for (int p = 0; p < 4; p++) {
                int rr = r + p * 32;
                float4 v = *(const float4*)(x + (size_t)(row0 + rr) * D_ + kt + c);
                As[c + 0][rr] = v.x; As[c + 1][rr] = v.y;
                As[c + 2][rr] = v.z; As[c + 3][rr] = v.w;
            }
        }
        // W tile: 32 d x 64 k, direct copy
        {
            int r = tid >> 4;            // 0..15
            int c = (tid & 15) * 4;
#pragma unroll
            for (int p = 0; p < 2; p++) {
                int rr = r + p * 16;
                *(float4*)&Bs[rr][c] = *(const float4*)(Wc + (size_t)(kt + rr) * K_ + c);
            }
        }
        __syncthreads();
#pragma unroll
        for (int kk = 0; kk < 32; kk++) {
            float af[8], bf[4];
            *(float4*)&af[0] = *(const float4*)&As[kk][ty * 8];
            *(float4*)&af[4] = *(const float4*)&As[kk][ty * 8 + 4];
            *(float4*)&bf[0] = *(const float4*)&Bs[kk][tx * 4];
#pragma unroll
            for (int i = 0; i < 8; i++)
#pragma unroll
                for (int j = 0; j < 4; j++)
                    acc[i][j] = fmaf(af[i], bf[j], acc[i][j]);
        }
        __syncthreads();
    }

    // epilogue: + bias, softmax over 64 cols (16 lanes x 4 cols), store a
    float bfr[4];
    *(float4*)bfr = *(const float4*)(bc + tx * 4);
    float asum_loc[4] = {0.f, 0.f, 0.f, 0.f};
#pragma unroll
    for (int i = 0; i < 8; i++) {
        float c0 = acc[i][0] + bfr[0];
        float c1 = acc[i][1] + bfr[1];
        float c2 = acc[i][2] + bfr[2];
        float c3 = acc[i][3] + bfr[3];
        float m = fmaxf(fmaxf(c0, c1), fmaxf(c2, c3));
#pragma unroll
        for (int o = 1; o < 16; o <<= 1)
            m = fmaxf(m, __shfl_xor_sync(0xffffffffu, m, o));
        float e0 = __expf(c0 - m), e1 = __expf(c1 - m);
        float e2 = __expf(c2 - m), e3 = __expf(c3 - m);
        float s = e0 + e1 + e2 + e3;
#pragma unroll
        for (int o = 1; o < 16; o <<= 1)
            s += __shfl_xor_sync(0xffffffffu, s, o);
        float inv = 1.0f / s;
        e0 *= inv; e1 *= inv; e2 *= inv; e3 *= inv;
        int row = row0 + ty * 8 + i;
        *(float4*)(g_a + (size_t)row * K_ + tx * 4) = make_float4(e0, e1, e2, e3);
        asum_loc[0] += e0; asum_loc[1] += e1; asum_loc[2] += e2; asum_loc[3] += e3;
    }
    // block-level a_sum reduction, one atomic per (block, k)
#pragma unroll
    for (int j = 0; j < 4; j++) red[ty][tx * 4 + j] = asum_loc[j];
    __syncthreads();
    if (tid < 64) {
        float s = 0.f;
#pragma unroll
        for (int t2 = 0; t2 < 16; t2++) s += red[t2][tid];
        atomicAdd(&g_asum[n * K_ + tid], s);
    }
}

// ---------------------------------------------------------------------------
// K2: per-batch VLAD GEMM  V[d,k] = sum_hw x[n,hw,d] * a[n,hw,k]
// Grid (4 d-tiles, 64 n). BM=128 (d), BN=64 (k), BK=32 (hw).
// Epilogue: V += a_sum[n,k]*C[d,k]; write to out [N,D,K]; accumulate colsq.
// ---------------------------------------------------------------------------
__launch_bounds__(256, 4)
__global__ void vlad_kernel(const float* __restrict__ x,
                            const float* __restrict__ Cc,
                            float* __restrict__ out) {
    __shared__ float As[32][128];   // [hw_k][d] -- natural load, no transpose
    __shared__ float Bs[32][64];    // [hw_k][k]
    __shared__ float red[16][64];

    const int tid = threadIdx.x;
    const int tx = tid & 15;
    const int ty = tid >> 4;
    const int n = blockIdx.y;
    const int m0 = blockIdx.x * 128;

    const float* xn = x + (size_t)n * HW_ * D_;
    const float* an = g_a + (size_t)n * HW_ * K_;

    float acc[8][4];
#pragma unroll
    for (int i = 0; i < 8; i++)
#pragma unroll
        for (int j = 0; j < 4; j++) acc[i][j] = 0.f;

    for (int kt = 0; kt < HW_; kt += 32) {
        {
            int r = tid >> 5;            // 0..7
            int c = (tid & 31) * 4;      // 0..124
#pragma unroll
            for (int p = 0; p < 4; p++) {
                int rr = r + p * 8;
                *(float4*)&As[rr][c] =
                    *(const float4*)(xn + (size_t)(kt + rr) * D_ + m0 + c);
            }
        }
        {
            int r = tid >> 4;
            int c = (tid & 15) * 4;
#pragma unroll
            for (int p = 0; p < 2; p++) {
                int rr = r + p * 16;
                *(float4*)&Bs[rr][c] = *(const float4*)(an + (size_t)(kt + rr) * K_ + c);
            }
        }
        __syncthreads();
#pragma unroll
        for (int kk = 0; kk < 32; kk++) {
            float af[8], bf[4];
            *(float4*)&af[0] = *(const float4*)&As[kk][ty * 8];
            *(float4*)&af[4] = *(const float4*)&As[kk][ty * 8 + 4];
            *(float4*)&bf[0] = *(const float4*)&Bs[kk][tx * 4];
#pragma unroll
            for (int i = 0; i < 8; i++)
#pragma unroll
                for (int j = 0; j < 4; j++)
                    acc[i][j] = fmaf(af[i], bf[j], acc[i][j]);
        }
        __syncthreads();
    }

    // epilogue: + a_sum*C, write v, accumulate column sum-of-squares
    float asv[4];
    *(float4*)asv = *(const float4*)(g_asum + n * K_ + tx * 4);
    float sq[4] = {0.f, 0.f, 0.f, 0.f};
#pragma unroll
    for (int i = 0; i < 8; i++) {
        int d = m0 + ty * 8 + i;
        float4 cc = *(const float4*)(Cc + (size_t)d * K_ + tx * 4);
        float v0 = fmaf(asv[0], cc.x, acc[i][0]);
        float v1 = fmaf(asv[1], cc.y, acc[i][1]);
        float v2 = fmaf(asv[2], cc.z, acc[i][2]);
        float v3 = fmaf(asv[3], cc.w, acc[i][3]);
        sq[0] = fmaf(v0, v0, sq[0]); sq[1] = fmaf(v1, v1, sq[1]);
        sq[2] = fmaf(v2, v2, sq[2]); sq[3] = fmaf(v3, v3, sq[3]);
        *(float4*)(out + ((size_t)n * D_ + d) * K_ + tx * 4) =
            make_float4(v0, v1, v2, v3);
    }
#pragma unroll
    for (int j = 0; j < 4; j++) red[ty][tx * 4 + j] = sq[j];
    __syncthreads();
    if (tid < 64) {
        float s = 0.f;
#pragma unroll
        for (int t2 = 0; t2 < 16; t2++) s += red[t2][tid];
        atomicAdd(&g_colsq[n * K_ + tid], s);
    }
}

// ---------------------------------------------------------------------------
// K3: two-level L2 normalization, in place on out. One block per n.
// intra: w = v / sqrt(S_k + eps); after intra, col sumsq = S_k/(S_k+eps)
// global: / sqrt( sum_k S_k/(S_k+eps) + eps )
// ---------------------------------------------------------------------------
__global__ void norm_kernel(float* __restrict__ out) {
    __shared__ float sc[64];
    __shared__ float contrib[64];
    __shared__ float ginv;

    const int n = blockIdx.x;
    const int tid = threadIdx.x;

    if (tid < 64) {
        float S = g_colsq[n * K_ + tid];
        sc[tid] = rsqrtf(S + EPSF);
        contrib[tid] = S / (S + EPSF);
    }
    __syncthreads();
    if (tid == 0) {
        float g = 0.f;
#pragma unroll
        for (int k = 0; k < 64; k++) g += contrib[k];
        ginv = rsqrtf(g + EPSF);
    }
    __syncthreads();
    if (tid < 64) sc[tid] *= ginv;
    __syncthreads();

    float* po = out + (size_t)n * D_ * K_;
    for (int e = tid * 4; e < D_ * K_; e += blockDim.x * 4) {
        float4 v = *(float4*)(po + e);
        int k = e & 63;            // e multiple of 4; 64 | row length
        v.x *= sc[k + 0]; v.y *= sc[k + 1];
        v.z *= sc[k + 2]; v.w *= sc[k + 3];
        *(float4*)(po + e) = v;
    }
}

// ---------------------------------------------------------------------------
extern "C" void kernel_launch(void* const* d_in, const int* in_sizes, int n_in,
                              void* d_out, int out_size) {
    const float* x  = (const float*)d_in[0];   // [64,32,32,512]
    const float* W  = (const float*)d_in[1];   // [512,64]
    const float* b  = (const float*)d_in[2];   // [64]
    const float* C  = (const float*)d_in[3];   // [512,64]
    float* out = (float*)d_out;                // [64, 32768]

    zero_kernel<<<16, 256>>>();
    assign_kernel<<<ROWS / 128, 256>>>(x, W, b);
    dim3 g2(D_ / 128, N_B);
    vlad_kernel<<<g2, 256>>>(x, C, out);
    norm_kernel<<<N_B, 256>>>(out);
}